// round 14
// baseline (speedup 1.0000x reference)
#include <cuda_runtime.h>
#include <cuda_fp16.h>
#include <cstdint>

#define B_ROWS  4096
#define IN_DIM  2048
#define OUT_DIM 2048

// ---------------------------------------------------------------------------
// Device scratch (static globals — no runtime allocation allowed)
// ---------------------------------------------------------------------------
__device__ __half g_Xh [(size_t)B_ROWS  * IN_DIM];   // half(clip(x,±5))   16MB
__device__ __half g_Wth[(size_t)OUT_DIM * IN_DIM];   // half(Ws+Wm+Wf)      8MB
__device__ __half g_Ph [(size_t)B_ROWS  * OUT_DIM];  // half(pre_act)      16MB

// ---------------------------------------------------------------------------
// PTX helpers (family-safe: cp.async, ldmatrix, mma.sync)
// ---------------------------------------------------------------------------
__device__ __forceinline__ uint32_t smem_u32(const void* p) {
    uint32_t a;
    asm("{ .reg .u64 t; cvta.to.shared.u64 t, %1; cvt.u32.u64 %0, t; }"
        : "=r"(a) : "l"(p));
    return a;
}

__device__ __forceinline__ uint32_t h2_bits(__half2 h) {
    return *reinterpret_cast<uint32_t*>(&h);
}

__device__ __forceinline__ float2 h2f2(uint32_t u) {
    __half2 h = *reinterpret_cast<__half2*>(&u);
    return __half22float2(h);
}

__device__ __forceinline__ void cp_async16(uint32_t dst, const void* src) {
    asm volatile("cp.async.cg.shared.global [%0], [%1], 16;"
                 :: "r"(dst), "l"(src));
}
#define CP_COMMIT() asm volatile("cp.async.commit_group;" ::: "memory")
#define CP_WAIT(n)  asm volatile("cp.async.wait_group %0;" :: "n"(n) : "memory")

#define LDSM_X4(r0, r1, r2, r3, addr)                                         \
    asm volatile("ldmatrix.sync.aligned.m8n8.x4.shared.b16 {%0,%1,%2,%3}, [%4];" \
                 : "=r"(r0), "=r"(r1), "=r"(r2), "=r"(r3) : "r"(addr))

// fp16-accumulate mma: D(half2 x2) += A x B. 2 dest regs instead of 4.
#define MMA_16816_H(d0, d1, a0, a1, a2, a3, b0, b1)                           \
    asm volatile("mma.sync.aligned.m16n8k16.row.col.f16.f16.f16.f16 "         \
                 "{%0,%1}, {%2,%3,%4,%5}, {%6,%7}, {%0,%1};"                  \
                 : "+r"(d0), "+r"(d1)                                         \
                 : "r"(a0), "r"(a1), "r"(a2), "r"(a3), "r"(b0), "r"(b1))

// ---------------------------------------------------------------------------
// Fused prepass. Heavy W-fold blocks first:
//   blocks [0, 2048)    : fold W_slow+W_medium+W_fast -> fp16
//   blocks [2048, 6144) : convert x (clip ±5 -> fp16)
// ---------------------------------------------------------------------------
__global__ void prep_kernel(const float4* __restrict__ x,
                            const float4* __restrict__ ws,
                            const float4* __restrict__ wm,
                            const float4* __restrict__ wf) {
    if (blockIdx.x < 2048) {
        int i = blockIdx.x * blockDim.x + threadIdx.x;
        float4 s0 = ws[2 * i], s1 = ws[2 * i + 1];
        float4 m0 = wm[2 * i], m1 = wm[2 * i + 1];
        float4 f0 = wf[2 * i], f1 = wf[2 * i + 1];
        uint4 ot;
        ot.x = h2_bits(__floats2half2_rn(s0.x + m0.x + f0.x, s0.y + m0.y + f0.y));
        ot.y = h2_bits(__floats2half2_rn(s0.z + m0.z + f0.z, s0.w + m0.w + f0.w));
        ot.z = h2_bits(__floats2half2_rn(s1.x + m1.x + f1.x, s1.y + m1.y + f1.y));
        ot.w = h2_bits(__floats2half2_rn(s1.z + m1.z + f1.z, s1.w + m1.w + f1.w));
        reinterpret_cast<uint4*>(g_Wth)[i] = ot;
    } else {
        int i = (blockIdx.x - 2048) * blockDim.x + threadIdx.x;
        float4 a = x[2 * i], b = x[2 * i + 1];
        a.x = fminf(fmaxf(a.x, -5.0f), 5.0f);  a.y = fminf(fmaxf(a.y, -5.0f), 5.0f);
        a.z = fminf(fmaxf(a.z, -5.0f), 5.0f);  a.w = fminf(fmaxf(a.w, -5.0f), 5.0f);
        b.x = fminf(fmaxf(b.x, -5.0f), 5.0f);  b.y = fminf(fmaxf(b.y, -5.0f), 5.0f);
        b.z = fminf(fmaxf(b.z, -5.0f), 5.0f);  b.w = fminf(fmaxf(b.w, -5.0f), 5.0f);
        uint4 o;
        o.x = h2_bits(__floats2half2_rn(a.x, a.y));
        o.y = h2_bits(__floats2half2_rn(a.z, a.w));
        o.z = h2_bits(__floats2half2_rn(b.x, b.y));
        o.w = h2_bits(__floats2half2_rn(b.z, b.w));
        reinterpret_cast<uint4*>(g_Xh)[i] = o;
    }
}

// ---------------------------------------------------------------------------
// fp16 mma.sync GEMM, 128x64 CTA tile at occupancy 4 (R13 shape), with
// fp16-ACCUMULATE inner mma: per K=32 chunk accumulate into fresh fp16 accs
// (2 roundings at partial magnitude ~0.1 -> ~2e-4 extra abs error), then
// promote into persistent fp32 accumulators. If legacy HMMA f16-acc issues at
// rt=8 (vs measured rt=16 for f32-acc) the MMA pipe time halves.
// ---------------------------------------------------------------------------
constexpr int BK = 32, STAGES = 3;
constexpr int ASTRIDE = 40;                        // halves per smem row (80B, CF)
constexpr int A_TILE_H  = 128 * ASTRIDE;           // 5120 halves
constexpr int B_TILE_H  = 64 * ASTRIDE;            // 2560 halves
constexpr int STG_H     = A_TILE_H + B_TILE_H;     // 7680
constexpr int SMEM_GEMM = STAGES * STG_H * 2;      // 46080
constexpr int NCHUNK = IN_DIM / BK;                // 64

__global__ __launch_bounds__(128, 4)
void gemm_fp16_kernel() {
    extern __shared__ __half sm[];
    const int tid  = threadIdx.x;
    const int wid  = tid >> 5;
    const int lane = tid & 31;
    const int bm = (blockIdx.x & 31) << 7;
    const int bn = (blockIdx.x >> 5) << 6;
    const __half* __restrict__ W = g_Wth;

    const int wmBase = (wid & 1) * 64;   // 2 m-warps
    const int wnBase = (wid >> 1) * 32;  // 2 n-warps

    const uint32_t sbase = smem_u32(sm);

    // Loader: A = 512 16B-chunks (4/thread), B = 256 (2/thread).
    const int arow0 = tid >> 2;
    const int aq    = tid & 3;
    const size_t aoffG = (size_t)aq * 8;
    const __half* gA = g_Xh + (size_t)(bm + arow0) * IN_DIM + aoffG;
    const __half* gB = W    + (size_t)(bn + arow0) * IN_DIM + aoffG;
    const uint32_t dA = (uint32_t)(arow0 * ASTRIDE + aq * 8) * 2;
    const uint32_t dB = (uint32_t)(arow0 * ASTRIDE + aq * 8) * 2 + A_TILE_H * 2;
    constexpr uint32_t AROWSTEP = (uint32_t)(32 * ASTRIDE) * 2;
    constexpr size_t   GROWSTEP = (size_t)32 * IN_DIM;

    auto load_stage = [&](int stage, int chunk) {
        const uint32_t sb = sbase + (uint32_t)stage * STG_H * 2;
        const size_t ko = (size_t)chunk * BK;
#pragma unroll
        for (int j = 0; j < 4; j++)
            cp_async16(sb + dA + j * AROWSTEP, gA + ko + j * GROWSTEP);
#pragma unroll
        for (int j = 0; j < 2; j++)
            cp_async16(sb + dB + j * AROWSTEP, gB + ko + j * GROWSTEP);
    };

    // ldmatrix addresses
    const int aRow = wmBase + (lane & 15);
    const int aCol = (lane >> 4) * 8;
    const int bRow = wnBase + (lane & 15);
    const uint32_t aOffBase = (uint32_t)(aRow * ASTRIDE + aCol) * 2;
    const uint32_t bOffBase = (uint32_t)(bRow * ASTRIDE + aCol) * 2 + A_TILE_H * 2;

    float acc[4][4][4];
#pragma unroll
    for (int i = 0; i < 4; i++)
#pragma unroll
        for (int j = 0; j < 4; j++)
#pragma unroll
            for (int q = 0; q < 4; q++) acc[i][j][q] = 0.0f;

#pragma unroll
    for (int s = 0; s < STAGES - 1; s++) { load_stage(s, s); CP_COMMIT(); }

    int stage = 0, pstage = STAGES - 1;
#pragma unroll 1
    for (int k = 0; k < NCHUNK; k++) {
        CP_WAIT(STAGES - 2);
        __syncthreads();
        const int kn = k + STAGES - 1;
        if (kn < NCHUNK) load_stage(pstage, kn);
        CP_COMMIT();

        const uint32_t sb = sbase + (uint32_t)stage * STG_H * 2;
        if (++stage == STAGES) stage = 0;
        if (++pstage == STAGES) pstage = 0;

        // Load B fragments for both kk halves of this K=32 chunk.
        uint32_t b[2][2][4];   // [kk][jj][frag]
#pragma unroll
        for (int kk = 0; kk < 2; kk++)
#pragma unroll
            for (int jj = 0; jj < 2; jj++)
                LDSM_X4(b[kk][jj][0], b[kk][jj][1], b[kk][jj][2], b[kk][jj][3],
                        sb + bOffBase + (uint32_t)(kk * 16) * 2
                           + (uint32_t)(jj * 16 * ASTRIDE) * 2);

#pragma unroll
        for (int i = 0; i < 4; i++) {
            uint32_t a0[4], a1[4];
            LDSM_X4(a0[0], a0[1], a0[2], a0[3],
                    sb + aOffBase + (uint32_t)(i * 16 * ASTRIDE) * 2);
            LDSM_X4(a1[0], a1[1], a1[2], a1[3],
                    sb + aOffBase + 32 + (uint32_t)(i * 16 * ASTRIDE) * 2);

            uint32_t hacc[4][2];   // 4 n-tiles x 2 half2 regs, fresh per chunk
#pragma unroll
            for (int j = 0; j < 4; j++) { hacc[j][0] = 0u; hacc[j][1] = 0u; }

#pragma unroll
            for (int jj = 0; jj < 2; jj++) {
                MMA_16816_H(hacc[2 * jj][0], hacc[2 * jj][1],
                            a0[0], a0[1], a0[2], a0[3],
                            b[0][jj][0], b[0][jj][2]);
                MMA_16816_H(hacc[2 * jj][0], hacc[2 * jj][1],
                            a1[0], a1[1], a1[2], a1[3],
                            b[1][jj][0], b[1][jj][2]);
                MMA_16816_H(hacc[2 * jj + 1][0], hacc[2 * jj + 1][1],
                            a0[0], a0[1], a0[2], a0[3],
                            b[0][jj][1], b[0][jj][3]);
                MMA_16816_H(hacc[2 * jj + 1][0], hacc[2 * jj + 1][1],
                            a1[0], a1[1], a1[2], a1[3],
                            b[1][jj][1], b[1][jj][3]);
            }

            // Promote chunk partials to fp32 accumulators
#pragma unroll
            for (int j = 0; j < 4; j++) {
                float2 lo = h2f2(hacc[j][0]);
                float2 hi = h2f2(hacc[j][1]);
                acc[i][j][0] += lo.x;  acc[i][j][1] += lo.y;
                acc[i][j][2] += hi.x;  acc[i][j][3] += hi.y;
            }
        }
    }

    // Epilogue: pack accumulators to fp16, 32-bit stores
    const int er = lane >> 2;
    const int ec = (lane & 3) * 2;
#pragma unroll
    for (int i = 0; i < 4; i++) {
        const int row0 = bm + wmBase + i * 16 + er;
#pragma unroll
        for (int j = 0; j < 4; j++) {
            const int col = bn + wnBase + j * 8 + ec;
            uint32_t v0 = h2_bits(__floats2half2_rn(acc[i][j][0], acc[i][j][1]));
            uint32_t v1 = h2_bits(__floats2half2_rn(acc[i][j][2], acc[i][j][3]));
            *reinterpret_cast<uint32_t*>(g_Ph + (size_t)row0 * OUT_DIM + col) = v0;
            *reinterpret_cast<uint32_t*>(g_Ph + (size_t)(row0 + 8) * OUT_DIM + col) = v1;
        }
    }
}

// ---------------------------------------------------------------------------
// Fused LayerNorm + soft clamp, reading fp16 P (8 halves/thread).
// tanh via saturating exp form: 5*tanh(y/5) = 5 - 10/(exp(0.4y)+1).
// ---------------------------------------------------------------------------
__global__ __launch_bounds__(256)
void ln_tanh_kernel(const float* __restrict__ gamma,
                    const float* __restrict__ beta,
                    float* __restrict__ out) {
    const int row = blockIdx.x;
    const uint4* p4 = reinterpret_cast<const uint4*>(g_Ph + (size_t)row * OUT_DIM);

    uint4 pv = p4[threadIdx.x];
    float2 f0 = __half22float2(*reinterpret_cast<__half2*>(&pv.x));
    float2 f1 = __half22float2(*reinterpret_cast<__half2*>(&pv.y));
    float2 f2 = __half22float2(*reinterpret_cast<__half2*>(&pv.z));
    float2 f3 = __half22float2(*reinterpret_cast<__half2*>(&pv.w));
    float p[8] = {f0.x, f0.y, f1.x, f1.y, f2.x, f2.y, f3.x, f3.y};

    float sum = 0.0f, sq = 0.0f;
#pragma unroll
    for (int q = 0; q < 8; q++) { sum += p[q]; sq += p[q] * p[q]; }

#pragma unroll
    for (int off = 16; off > 0; off >>= 1) {
        sum += __shfl_xor_sync(0xFFFFFFFFu, sum, off);
        sq  += __shfl_xor_sync(0xFFFFFFFFu, sq,  off);
    }
    __shared__ float rs[8], rq[8];
    __shared__ float s_mu, s_inv;
    int lane = threadIdx.x & 31, wrp = threadIdx.x >> 5;
    if (lane == 0) { rs[wrp] = sum; rq[wrp] = sq; }
    __syncthreads();
    if (threadIdx.x == 0) {
        float ts = 0.0f, tq = 0.0f;
#pragma unroll
        for (int i = 0; i < 8; i++) { ts += rs[i]; tq += rq[i]; }
        float mu  = ts * (1.0f / OUT_DIM);
        float var = tq * (1.0f / OUT_DIM) - mu * mu;
        s_mu  = mu;
        s_inv = rsqrtf(fmaxf(var, 0.0f) + 1e-5f);
    }
    __syncthreads();
    const float mu = s_mu, inv = s_inv;

    const float4* g4 = reinterpret_cast<const float4*>(gamma);
    const float4* b4 = reinterpret_cast<const float4*>(beta);
    float4* o4 = reinterpret_cast<float4*>(out + (size_t)row * OUT_DIM);

#pragma unroll
    for (int it = 0; it < 2; it++) {
        int j4 = 2 * threadIdx.x + it;
        float4 gv = g4[j4];
        float4 bv = b4[j4];
        float ga[4] = {gv.x, gv.y, gv.z, gv.w};
        float ba[4] = {bv.x, bv.y, bv.z, bv.w};
        float* pp = &p[it * 4];
        float4 ov;
        float* oa = reinterpret_cast<float*>(&ov);
#pragma unroll
        for (int q = 0; q < 4; q++) {
            float nv = (pp[q] - mu) * inv * ga[q] + ba[q];
            float e = __expf(0.4f * nv);
            oa[q] = 5.0f - 10.0f * __frcp_rn(e + 1.0f);
        }
        o4[j4] = ov;
    }
}

// ---------------------------------------------------------------------------
extern "C" void kernel_launch(void* const* d_in, const int* in_sizes, int n_in,
                              void* d_out, int out_size) {
    const float* x     = (const float*)d_in[0];
    const float* Wslow = (const float*)d_in[1];
    const float* Wmed  = (const float*)d_in[2];
    const float* Wfast = (const float*)d_in[3];
    const float* gamma = (const float*)d_in[4];
    const float* beta  = (const float*)d_in[5];
    float* out = (float*)d_out;

    prep_kernel<<<6144, 256>>>(
        reinterpret_cast<const float4*>(x),
        reinterpret_cast<const float4*>(Wslow),
        reinterpret_cast<const float4*>(Wmed),
        reinterpret_cast<const float4*>(Wfast));

    cudaFuncSetAttribute(gemm_fp16_kernel,
                         cudaFuncAttributeMaxDynamicSharedMemorySize, SMEM_GEMM);
    gemm_fp16_kernel<<<1024, 128, SMEM_GEMM>>>();

    ln_tanh_kernel<<<B_ROWS, 256>>>(gamma, beta, out);
}

// round 15
// speedup vs baseline: 1.0696x; 1.0696x over previous
#include <cuda_runtime.h>
#include <cuda_fp16.h>
#include <cstdint>

#define B_ROWS  4096
#define IN_DIM  2048
#define OUT_DIM 2048

// ---------------------------------------------------------------------------
// Device scratch (static globals — no runtime allocation allowed)
// ---------------------------------------------------------------------------
__device__ __half g_Xh [(size_t)B_ROWS  * IN_DIM];   // half(clip(x,±5))   16MB
__device__ __half g_Wth[(size_t)OUT_DIM * IN_DIM];   // half(Ws+Wm+Wf)      8MB
__device__ __half g_Ph [(size_t)B_ROWS  * OUT_DIM];  // half(pre_act)      16MB

// ---------------------------------------------------------------------------
// PTX helpers (family-safe: cp.async, ldmatrix, mma.sync)
// ---------------------------------------------------------------------------
__device__ __forceinline__ uint32_t smem_u32(const void* p) {
    uint32_t a;
    asm("{ .reg .u64 t; cvta.to.shared.u64 t, %1; cvt.u32.u64 %0, t; }"
        : "=r"(a) : "l"(p));
    return a;
}

__device__ __forceinline__ uint32_t h2_bits(__half2 h) {
    return *reinterpret_cast<uint32_t*>(&h);
}

__device__ __forceinline__ void cp_async16(uint32_t dst, const void* src) {
    asm volatile("cp.async.cg.shared.global [%0], [%1], 16;"
                 :: "r"(dst), "l"(src));
}
#define CP_COMMIT() asm volatile("cp.async.commit_group;" ::: "memory")
#define CP_WAIT(n)  asm volatile("cp.async.wait_group %0;" :: "n"(n) : "memory")

#define LDSM_X4(r0, r1, r2, r3, addr)                                         \
    asm volatile("ldmatrix.sync.aligned.m8n8.x4.shared.b16 {%0,%1,%2,%3}, [%4];" \
                 : "=r"(r0), "=r"(r1), "=r"(r2), "=r"(r3) : "r"(addr))

#define MMA_16816(d0, d1, d2, d3, a0, a1, a2, a3, b0, b1)                     \
    asm volatile("mma.sync.aligned.m16n8k16.row.col.f32.f16.f16.f32 "         \
                 "{%0,%1,%2,%3}, {%4,%5,%6,%7}, {%8,%9}, {%0,%1,%2,%3};"      \
                 : "+f"(d0), "+f"(d1), "+f"(d2), "+f"(d3)                     \
                 : "r"(a0), "r"(a1), "r"(a2), "r"(a3), "r"(b0), "r"(b1))

// ---------------------------------------------------------------------------
// Fused prepass, high-MLP form.
//   blocks [0, 1024)    : fold W_slow+W_medium+W_fast -> fp16 (12 loads in flight)
//   blocks [1024, 3072) : convert x (clip ±5 -> fp16)         (4 loads in flight)
// Each thread: 2 independent 32B-contiguous float4-pairs -> 2 uint4 stores.
// ---------------------------------------------------------------------------
__device__ __forceinline__ uint4 pack2(float4 a, float4 b) {
    uint4 o;
    o.x = h2_bits(__floats2half2_rn(a.x, a.y));
    o.y = h2_bits(__floats2half2_rn(a.z, a.w));
    o.z = h2_bits(__floats2half2_rn(b.x, b.y));
    o.w = h2_bits(__floats2half2_rn(b.z, b.w));
    return o;
}

__device__ __forceinline__ float4 clip4(float4 v) {
    v.x = fminf(fmaxf(v.x, -5.0f), 5.0f);
    v.y = fminf(fmaxf(v.y, -5.0f), 5.0f);
    v.z = fminf(fmaxf(v.z, -5.0f), 5.0f);
    v.w = fminf(fmaxf(v.w, -5.0f), 5.0f);
    return v;
}

__device__ __forceinline__ float4 add3(float4 a, float4 b, float4 c) {
    return make_float4(a.x + b.x + c.x, a.y + b.y + c.y,
                       a.z + b.z + c.z, a.w + b.w + c.w);
}

__global__ void prep_kernel(const float4* __restrict__ x,
                            const float4* __restrict__ ws,
                            const float4* __restrict__ wm,
                            const float4* __restrict__ wf) {
    const int t = threadIdx.x;
    if (blockIdx.x < 1024) {
        const size_t base = (size_t)blockIdx.x * 1024;     // float4 units
        const size_t i0 = base + 2 * t;                    // pair A
        const size_t i1 = base + 512 + 2 * t;              // pair B
        // 12 independent loads in flight
        float4 s0 = ws[i0], s1 = ws[i0 + 1], s2 = ws[i1], s3 = ws[i1 + 1];
        float4 m0 = wm[i0], m1 = wm[i0 + 1], m2 = wm[i1], m3 = wm[i1 + 1];
        float4 f0 = wf[i0], f1 = wf[i0 + 1], f2 = wf[i1], f3 = wf[i1 + 1];
        uint4* o = reinterpret_cast<uint4*>(g_Wth);
        o[base / 2 + t]       = pack2(add3(s0, m0, f0), add3(s1, m1, f1));
        o[base / 2 + 256 + t] = pack2(add3(s2, m2, f2), add3(s3, m3, f3));
    } else {
        const size_t base = (size_t)(blockIdx.x - 1024) * 1024;
        const size_t i0 = base + 2 * t;
        const size_t i1 = base + 512 + 2 * t;
        float4 a0 = x[i0], a1 = x[i0 + 1], a2 = x[i1], a3 = x[i1 + 1];
        uint4* o = reinterpret_cast<uint4*>(g_Xh);
        o[base / 2 + t]       = pack2(clip4(a0), clip4(a1));
        o[base / 2 + 256 + t] = pack2(clip4(a2), clip4(a3));
    }
}

// ---------------------------------------------------------------------------
// fp16 mma.sync GEMM, 128x64 CTA tile at occupancy 4 (R13 proven shape).
// 1024 CTAs: bm = (b & 31)*128, bn = (b >> 5)*64.
// 128 threads = 4 warps as 2(m) x 2(n); warp tile 64x32.
// 3-stage cp.async pipeline; occ-4 co-residency supplies latency hiding.
// ---------------------------------------------------------------------------
constexpr int BK = 32, STAGES = 3;
constexpr int ASTRIDE = 40;                        // halves per smem row (80B, CF)
constexpr int A_TILE_H  = 128 * ASTRIDE;           // 5120 halves
constexpr int B_TILE_H  = 64 * ASTRIDE;            // 2560 halves
constexpr int STG_H     = A_TILE_H + B_TILE_H;     // 7680
constexpr int SMEM_GEMM = STAGES * STG_H * 2;      // 46080
constexpr int NCHUNK = IN_DIM / BK;                // 64

__global__ __launch_bounds__(128, 4)
void gemm_fp16_kernel() {
    extern __shared__ __half sm[];
    const int tid  = threadIdx.x;
    const int wid  = tid >> 5;
    const int lane = tid & 31;
    const int bm = (blockIdx.x & 31) << 7;
    const int bn = (blockIdx.x >> 5) << 6;
    const __half* __restrict__ W = g_Wth;

    const int wmBase = (wid & 1) * 64;   // 2 m-warps
    const int wnBase = (wid >> 1) * 32;  // 2 n-warps

    const uint32_t sbase = smem_u32(sm);

    // Loader: A = 512 16B-chunks (4/thread), B = 256 (2/thread).
    const int arow0 = tid >> 2;
    const int aq    = tid & 3;
    const size_t aoffG = (size_t)aq * 8;
    const __half* gA = g_Xh + (size_t)(bm + arow0) * IN_DIM + aoffG;
    const __half* gB = W    + (size_t)(bn + arow0) * IN_DIM + aoffG;
    const uint32_t dA = (uint32_t)(arow0 * ASTRIDE + aq * 8) * 2;
    const uint32_t dB = (uint32_t)(arow0 * ASTRIDE + aq * 8) * 2 + A_TILE_H * 2;
    constexpr uint32_t AROWSTEP = (uint32_t)(32 * ASTRIDE) * 2;
    constexpr size_t   GROWSTEP = (size_t)32 * IN_DIM;

    auto load_stage = [&](int stage, int chunk) {
        const uint32_t sb = sbase + (uint32_t)stage * STG_H * 2;
        const size_t ko = (size_t)chunk * BK;
#pragma unroll
        for (int j = 0; j < 4; j++)
            cp_async16(sb + dA + j * AROWSTEP, gA + ko + j * GROWSTEP);
#pragma unroll
        for (int j = 0; j < 2; j++)
            cp_async16(sb + dB + j * AROWSTEP, gB + ko + j * GROWSTEP);
    };

    // ldmatrix addresses
    const int aRow = wmBase + (lane & 15);
    const int aCol = (lane >> 4) * 8;
    const int bRow = wnBase + (lane & 15);
    const uint32_t aOffBase = (uint32_t)(aRow * ASTRIDE + aCol) * 2;
    const uint32_t bOffBase = (uint32_t)(bRow * ASTRIDE + aCol) * 2 + A_TILE_H * 2;

    float acc[4][4][4];
#pragma unroll
    for (int i = 0; i < 4; i++)
#pragma unroll
        for (int j = 0; j < 4; j++)
#pragma unroll
            for (int q = 0; q < 4; q++) acc[i][j][q] = 0.0f;

    // Prologue: chunks 0,1 into stages 0,1
#pragma unroll
    for (int s = 0; s < STAGES - 1; s++) { load_stage(s, s); CP_COMMIT(); }

    int stage = 0, pstage = STAGES - 1;
#pragma unroll 1
    for (int k = 0; k < NCHUNK; k++) {
        CP_WAIT(STAGES - 2);
        __syncthreads();
        const int kn = k + STAGES - 1;
        if (kn < NCHUNK) load_stage(pstage, kn);
        CP_COMMIT();

        const uint32_t sb = sbase + (uint32_t)stage * STG_H * 2;
        if (++stage == STAGES) stage = 0;
        if (++pstage == STAGES) pstage = 0;

#pragma unroll
        for (int kk = 0; kk < 2; kk++) {
            const uint32_t kOff = (uint32_t)(kk * 16) * 2;
            uint32_t a[4][4];
#pragma unroll
            for (int i = 0; i < 4; i++)
                LDSM_X4(a[i][0], a[i][1], a[i][2], a[i][3],
                        sb + aOffBase + kOff + (uint32_t)(i * 16 * ASTRIDE) * 2);
            uint32_t b[2][4];
#pragma unroll
            for (int jj = 0; jj < 2; jj++)
                LDSM_X4(b[jj][0], b[jj][1], b[jj][2], b[jj][3],
                        sb + bOffBase + kOff + (uint32_t)(jj * 16 * ASTRIDE) * 2);
#pragma unroll
            for (int i = 0; i < 4; i++)
#pragma unroll
                for (int jj = 0; jj < 2; jj++) {
                    MMA_16816(acc[i][2 * jj][0], acc[i][2 * jj][1],
                              acc[i][2 * jj][2], acc[i][2 * jj][3],
                              a[i][0], a[i][1], a[i][2], a[i][3],
                              b[jj][0], b[jj][2]);
                    MMA_16816(acc[i][2 * jj + 1][0], acc[i][2 * jj + 1][1],
                              acc[i][2 * jj + 1][2], acc[i][2 * jj + 1][3],
                              a[i][0], a[i][1], a[i][2], a[i][3],
                              b[jj][1], b[jj][3]);
                }
        }
    }

    // Epilogue: pack accumulators to fp16, 32-bit stores
    const int er = lane >> 2;
    const int ec = (lane & 3) * 2;
#pragma unroll
    for (int i = 0; i < 4; i++) {
        const int row0 = bm + wmBase + i * 16 + er;
#pragma unroll
        for (int j = 0; j < 4; j++) {
            const int col = bn + wnBase + j * 8 + ec;
            uint32_t v0 = h2_bits(__floats2half2_rn(acc[i][j][0], acc[i][j][1]));
            uint32_t v1 = h2_bits(__floats2half2_rn(acc[i][j][2], acc[i][j][3]));
            *reinterpret_cast<uint32_t*>(g_Ph + (size_t)row0 * OUT_DIM + col) = v0;
            *reinterpret_cast<uint32_t*>(g_Ph + (size_t)(row0 + 8) * OUT_DIM + col) = v1;
        }
    }
}

// ---------------------------------------------------------------------------
// Fused LayerNorm + soft clamp, reading fp16 P (8 halves/thread).
// tanh via saturating exp form: 5*tanh(y/5) = 5 - 10/(exp(0.4y)+1).
// ---------------------------------------------------------------------------
__global__ __launch_bounds__(256)
void ln_tanh_kernel(const float* __restrict__ gamma,
                    const float* __restrict__ beta,
                    float* __restrict__ out) {
    const int row = blockIdx.x;
    const uint4* p4 = reinterpret_cast<const uint4*>(g_Ph + (size_t)row * OUT_DIM);

    uint4 pv = p4[threadIdx.x];
    float2 f0 = __half22float2(*reinterpret_cast<__half2*>(&pv.x));
    float2 f1 = __half22float2(*reinterpret_cast<__half2*>(&pv.y));
    float2 f2 = __half22float2(*reinterpret_cast<__half2*>(&pv.z));
    float2 f3 = __half22float2(*reinterpret_cast<__half2*>(&pv.w));
    float p[8] = {f0.x, f0.y, f1.x, f1.y, f2.x, f2.y, f3.x, f3.y};

    float sum = 0.0f, sq = 0.0f;
#pragma unroll
    for (int q = 0; q < 8; q++) { sum += p[q]; sq += p[q] * p[q]; }

#pragma unroll
    for (int off = 16; off > 0; off >>= 1) {
        sum += __shfl_xor_sync(0xFFFFFFFFu, sum, off);
        sq  += __shfl_xor_sync(0xFFFFFFFFu, sq,  off);
    }
    __shared__ float rs[8], rq[8];
    __shared__ float s_mu, s_inv;
    int lane = threadIdx.x & 31, wrp = threadIdx.x >> 5;
    if (lane == 0) { rs[wrp] = sum; rq[wrp] = sq; }
    __syncthreads();
    if (threadIdx.x == 0) {
        float ts = 0.0f, tq = 0.0f;
#pragma unroll
        for (int i = 0; i < 8; i++) { ts += rs[i]; tq += rq[i]; }
        float mu  = ts * (1.0f / OUT_DIM);
        float var = tq * (1.0f / OUT_DIM) - mu * mu;
        s_mu  = mu;
        s_inv = rsqrtf(fmaxf(var, 0.0f) + 1e-5f);
    }
    __syncthreads();
    const float mu = s_mu, inv = s_inv;

    const float4* g4 = reinterpret_cast<const float4*>(gamma);
    const float4* b4 = reinterpret_cast<const float4*>(beta);
    float4* o4 = reinterpret_cast<float4*>(out + (size_t)row * OUT_DIM);

#pragma unroll
    for (int it = 0; it < 2; it++) {
        int j4 = 2 * threadIdx.x + it;
        float4 gv = g4[j4];
        float4 bv = b4[j4];
        float ga[4] = {gv.x, gv.y, gv.z, gv.w};
        float ba[4] = {bv.x, bv.y, bv.z, bv.w};
        float* pp = &p[it * 4];
        float4 ov;
        float* oa = reinterpret_cast<float*>(&ov);
#pragma unroll
        for (int q = 0; q < 4; q++) {
            float nv = (pp[q] - mu) * inv * ga[q] + ba[q];
            float e = __expf(0.4f * nv);
            oa[q] = 5.0f - 10.0f * __frcp_rn(e + 1.0f);
        }
        o4[j4] = ov;
    }
}

// ---------------------------------------------------------------------------
extern "C" void kernel_launch(void* const* d_in, const int* in_sizes, int n_in,
                              void* d_out, int out_size) {
    const float* x     = (const float*)d_in[0];
    const float* Wslow = (const float*)d_in[1];
    const float* Wmed  = (const float*)d_in[2];
    const float* Wfast = (const float*)d_in[3];
    const float* gamma = (const float*)d_in[4];
    const float* beta  = (const float*)d_in[5];
    float* out = (float*)d_out;

    prep_kernel<<<3072, 256>>>(
        reinterpret_cast<const float4*>(x),
        reinterpret_cast<const float4*>(Wslow),
        reinterpret_cast<const float4*>(Wmed),
        reinterpret_cast<const float4*>(Wfast));

    cudaFuncSetAttribute(gemm_fp16_kernel,
                         cudaFuncAttributeMaxDynamicSharedMemorySize, SMEM_GEMM);
    gemm_fp16_kernel<<<1024, 128, SMEM_GEMM>>>();

    ln_tanh_kernel<<<B_ROWS, 256>>>(gamma, beta, out);
}